// round 8
// baseline (speedup 1.0000x reference)
#include <cuda_runtime.h>

// Problem dims
#define B_  1024
#define S_  128
#define LP_ 14
#define K_  3
#define CE_ 6
#define WE_ 10
#define LF_ 4
#define H_  6
#define V_  50000
#define A_  100
#define T_  135
#define D_  14      // WE + LF
#define LW_ 12      // LP - K + 1
#define TS  16      // lstm tile steps

// Scratch (no allocation allowed -> device globals)
__device__ float g_pre[(size_t)B_ * 2 * S_ * 24];  // [b][dir][s][24] gate pre-activations
__device__ float g_h[(size_t)B_ * S_ * 12];        // [B,S,12] = [hf | hb]
__device__ float g_pd[A_ * 12];                    // pd[c][l*3+k] char-conv table

__device__ __forceinline__ float tanh_fast(float x) {
    float y;
    asm("tanh.approx.f32 %0, %1;" : "=f"(y) : "f"(x));
    return y;
}

// packed f32x2 helpers
__device__ __forceinline__ unsigned long long pack2(float lo, float hi) {
    unsigned long long r;
    asm("mov.b64 %0, {%1, %2};" : "=l"(r) : "f"(lo), "f"(hi));
    return r;
}
__device__ __forceinline__ void unpack2(float& lo, float& hi, unsigned long long v) {
    asm("mov.b64 {%0, %1}, %2;" : "=f"(lo), "=f"(hi) : "l"(v));
}
__device__ __forceinline__ unsigned long long fma2(unsigned long long a,
                                                   unsigned long long b,
                                                   unsigned long long c) {
    unsigned long long d;
    asm("fma.rn.f32x2 %0, %1, %2, %3;" : "=l"(d) : "l"(a), "l"(b), "l"(c));
    return d;
}

// ---------------------------------------------------------------------------
// Kernel 0: pd table. pd[c][l][k] = <char_emb[c], Wc[l, k*CE:(k+1)*CE]>,
// with bc[l] folded into the k=2 slot.
// ---------------------------------------------------------------------------
__global__ void pd_kernel(const float* __restrict__ char_emb,
                          const float* __restrict__ Wc,
                          const float* __restrict__ bc)
{
    int idx = blockIdx.x * blockDim.x + threadIdx.x;
    if (idx >= A_ * 12) return;
    int c = idx / 12, r = idx - c * 12;
    int l = r / 3,   k = r - l * 3;
    float acc = (k == 2) ? bc[l] : 0.0f;
#pragma unroll
    for (int e = 0; e < CE_; e++)
        acc = fmaf(char_emb[c * CE_ + e], Wc[l * (K_ * CE_) + k * CE_ + e], acc);
    g_pd[idx] = acc;
}

// ---------------------------------------------------------------------------
// Kernel 1: embedding + char CNN + gate pre-activations (thread per word).
// Computes x[16] = [we(10) | char_repr(4) | 1 | 0], then immediately the
// 48 gate pre-activations (both directions) pre[g] = <x, W[g]> where W[g]
// is the 16-padded Wih row with bias in slot 14. LSTM never touches x.
// ---------------------------------------------------------------------------
__global__ __launch_bounds__(256) void embed_cnn_kernel(
    const int*   __restrict__ word_idx,
    const int*   __restrict__ char_idx,
    const float* __restrict__ word_emb,
    const float* __restrict__ Wih_f, const float* __restrict__ b_f,
    const float* __restrict__ Wih_b, const float* __restrict__ b_b)
{
    __shared__ float s_pd[A_ * 12];
    __shared__ int   s_ci[256 * LP_];
    __shared__ float s_w[48 * 16];   // [gate(f24,b24)][16]: w(14), bias, 0

    for (int i = threadIdx.x; i < A_ * 12; i += 256) s_pd[i] = g_pd[i];

    for (int i = threadIdx.x; i < 48 * 16; i += 256) {
        int r = i >> 4, j = i & 15;
        float v = 0.0f;
        if (j < 14)       v = (r < 24) ? Wih_f[r * 14 + j] : Wih_b[(r - 24) * 14 + j];
        else if (j == 14) v = (r < 24) ? b_f[r] : b_b[r - 24];
        s_w[i] = v;
    }

    int wbase = blockIdx.x * 256;
    const int* ci_g = char_idx + (size_t)wbase * LP_;
    for (int i = threadIdx.x; i < 256 * LP_; i += 256) s_ci[i] = ci_g[i];
    __syncthreads();

    int t = wbase + threadIdx.x;

    int wi = word_idx[t];
    const float2* wrow = reinterpret_cast<const float2*>(word_emb + (size_t)wi * WE_);
    float2 w0 = wrow[0], w1 = wrow[1], w2 = wrow[2], w3 = wrow[3], w4 = wrow[4];

    const int* ci = s_ci + threadIdx.x * LP_;

    float A1[LF_], A2[LF_], mx[LF_];
#pragma unroll
    for (int l = 0; l < LF_; l++) mx[l] = -1e30f;

#pragma unroll
    for (int p = 0; p < LP_; p++) {
        int c = ci[p];
        const float4* pr = reinterpret_cast<const float4*>(s_pd + c * 12);
        float4 r0 = pr[0], r1 = pr[1], r2 = pr[2];
        float k0[LF_] = {r0.x, r0.w, r1.z, r2.y};
        float k1[LF_] = {r0.y, r1.x, r1.w, r2.z};
        float k2[LF_] = {r0.z, r1.y, r2.x, r2.w};
        if (p >= 2) {
#pragma unroll
            for (int l = 0; l < LF_; l++)
                mx[l] = fmaxf(mx[l], A2[l] + k2[l]);
        }
#pragma unroll
        for (int l = 0; l < LF_; l++) {
            A2[l] = (p >= 1) ? (A1[l] + k1[l]) : 0.0f;
            A1[l] = k0[l];
        }
    }

    float x[16] = {w0.x, w0.y, w1.x, w1.y, w2.x, w2.y, w3.x, w3.y, w4.x, w4.y,
                   mx[0], mx[1], mx[2], mx[3], 1.0f, 0.0f};

    int b = t >> 7, s = t & (S_ - 1);

#pragma unroll
    for (int dir = 0; dir < 2; dir++) {
        float* dst = g_pre + (((size_t)(b * 2 + dir)) * S_ + s) * 24;
#pragma unroll
        for (int q = 0; q < 6; q++) {
            float a[4];
#pragma unroll
            for (int k = 0; k < 4; k++) {
                const float4* wr = reinterpret_cast<const float4*>(
                    s_w + (dir * 24 + q * 4 + k) * 16);
                float4 u0 = wr[0], u1 = wr[1], u2 = wr[2], u3 = wr[3];
                float acc;
                acc = x[0] * u0.x;
                acc = fmaf(x[1],  u0.y, acc); acc = fmaf(x[2],  u0.z, acc);
                acc = fmaf(x[3],  u0.w, acc); acc = fmaf(x[4],  u1.x, acc);
                acc = fmaf(x[5],  u1.y, acc); acc = fmaf(x[6],  u1.z, acc);
                acc = fmaf(x[7],  u1.w, acc); acc = fmaf(x[8],  u2.x, acc);
                acc = fmaf(x[9],  u2.y, acc); acc = fmaf(x[10], u2.z, acc);
                acc = fmaf(x[11], u2.w, acc); acc = fmaf(x[12], u3.x, acc);
                acc = fmaf(x[13], u3.y, acc); acc = fmaf(x[14], u3.z, acc);
                a[k] = acc;
            }
            reinterpret_cast<float4*>(dst)[q] = make_float4(a[0], a[1], a[2], a[3]);
        }
    }
}

// ---------------------------------------------------------------------------
// Kernel 2: bidirectional LSTM recurrence only. One warp per (batch, dir).
// Lane g<24 owns gate row g (torch i,f,g,o). Pre-activations streamed through
// smem in 16-step tiles; per step: 1 LDS + h-broadcast shfl + 6 FMA + tanh
// + gate shfl + cell update.
// ---------------------------------------------------------------------------
template <int DIR>
__device__ __forceinline__ void lstm_run(
    int b, int lid, float* sx, const float* __restrict__ Whh)
{
    int g = (lid < 24) ? lid : 0;
    float whh[H_];
#pragma unroll
    for (int j = 0; j < H_; j++) whh[j] = Whh[g * H_ + j];

    bool  is_g = (lid >= 12 && lid < 18);
    float s1 = is_g ? 1.0f : 0.5f;
    float a1 = is_g ? 1.0f : 0.5f;
    float b1 = is_g ? 0.0f : 0.5f;

    size_t hbase  = (size_t)b * S_;
    const float* pre = g_pre + ((size_t)(b * 2 + DIR)) * S_ * 24;

    float h = 0.0f, c = 0.0f;

    // prefetch first tile (16 steps x 24 floats = 96 float4)
    float4 v0, v1, v2;
    {
        int t0 = DIR ? (S_ - TS) : 0;
        const float4* src = reinterpret_cast<const float4*>(pre + t0 * 24);
        v0 = src[lid]; v1 = src[lid + 32]; v2 = src[lid + 64];
    }

#pragma unroll 1
    for (int tile = 0; tile < S_ / TS; tile++) {
        int tnat = DIR ? (S_ / TS - 1 - tile) : tile;
        int t0   = tnat * TS;

        float4* sp = reinterpret_cast<float4*>(sx);
        sp[lid] = v0; sp[lid + 32] = v1; sp[lid + 64] = v2;
        __syncwarp();

        if (tile + 1 < S_ / TS) {
            int n0 = (DIR ? (tnat - 1) : (tnat + 1)) * TS;
            const float4* src = reinterpret_cast<const float4*>(pre + n0 * 24);
            v0 = src[lid]; v1 = src[lid + 32]; v2 = src[lid + 64];
        }

#pragma unroll
        for (int i = 0; i < TS; i++) {
            int slot = DIR ? (TS - 1 - i) : i;
            int s    = t0 + slot;

            float accx = sx[slot * 24 + g];

            float h0 = __shfl_sync(0xffffffffu, h, 0);
            float h1 = __shfl_sync(0xffffffffu, h, 1);
            float h2 = __shfl_sync(0xffffffffu, h, 2);
            float h3 = __shfl_sync(0xffffffffu, h, 3);
            float h4 = __shfl_sync(0xffffffffu, h, 4);
            float h5 = __shfl_sync(0xffffffffu, h, 5);
            float acc0 = fmaf(h0, whh[0], accx);
            acc0 = fmaf(h1, whh[1], acc0);
            acc0 = fmaf(h2, whh[2], acc0);
            float acc1 = h3 * whh[3];
            acc1 = fmaf(h4, whh[4], acc1);
            acc1 = fmaf(h5, whh[5], acc1);
            float acc = acc0 + acc1;

            float act = fmaf(tanh_fast(acc * s1), a1, b1);

            float fv = __shfl_sync(0xffffffffu, act, lid + 6);
            float gv = __shfl_sync(0xffffffffu, act, lid + 12);
            float ov = __shfl_sync(0xffffffffu, act, lid + 18);

            if (lid < H_) {
                c = fmaf(fv, c, act * gv);
                h = ov * tanh_fast(c);
                g_h[(hbase + s) * 12 + DIR * H_ + lid] = h;
            }
        }
        __syncwarp();
    }
}

__global__ __launch_bounds__(128) void lstm_kernel(
    const float* __restrict__ Whh_f, const float* __restrict__ Whh_b)
{
    __shared__ float s_x[4][TS * 24];
    int wip  = threadIdx.x >> 5;
    int lid  = threadIdx.x & 31;
    int warp = blockIdx.x * 4 + wip;
    int dir  = warp >> 10;
    int b    = warp & 1023;
    float* sx = s_x[wip];

    if (dir == 0) lstm_run<0>(b, lid, sx, Whh_f);
    else          lstm_run<1>(b, lid, sx, Whh_b);
}

// ---------------------------------------------------------------------------
// Kernel 3: tag projection + log_softmax, WPW words per warp.
// Lane lid owns tag rows {lid, lid+32, lid+64, lid+96, lid+128}. Weights are
// packed ACROSS ROW PAIRS {w_r0,w_r1} (no duplication -> no spills); the
// word's h value is broadcast as {o,o}. Row 4 (7 lanes) is scalar.
// No max shift (logits are O(1)).
// ---------------------------------------------------------------------------
#define WPW 16
__global__ __launch_bounds__(256) void proj_softmax_kernel(
    const float* __restrict__ Wt,
    const float* __restrict__ bt,
    float* __restrict__ out)
{
    int warp = (blockIdx.x * blockDim.x + threadIdx.x) >> 5;
    int lid  = threadIdx.x & 31;

    bool v4 = lid < (T_ - 128);
    int  t4 = v4 ? (lid + 128) : 0;

    // load 4 full rows + optional 5th
    float wr[4][12];
#pragma unroll
    for (int r = 0; r < 4; r++) {
        const float4* p = reinterpret_cast<const float4*>(Wt + (lid + 32 * r) * 12);
        float4 a = p[0], b = p[1], c = p[2];
        wr[r][0] = a.x; wr[r][1] = a.y; wr[r][2]  = a.z; wr[r][3]  = a.w;
        wr[r][4] = b.x; wr[r][5] = b.y; wr[r][6]  = b.z; wr[r][7]  = b.w;
        wr[r][8] = c.x; wr[r][9] = c.y; wr[r][10] = c.z; wr[r][11] = c.w;
    }
    float w4[12];
    {
        const float4* p = reinterpret_cast<const float4*>(Wt + t4 * 12);
        float4 a = p[0], b = p[1], c = p[2];
        float tmp[12] = {a.x, a.y, a.z, a.w, b.x, b.y, b.z, b.w, c.x, c.y, c.z, c.w};
#pragma unroll
        for (int j = 0; j < 12; j++) w4[j] = v4 ? tmp[j] : 0.0f;
    }

    unsigned long long wpA[12], wpB[12];
#pragma unroll
    for (int j = 0; j < 12; j++) {
        wpA[j] = pack2(wr[0][j], wr[1][j]);
        wpB[j] = pack2(wr[2][j], wr[3][j]);
    }
    unsigned long long zbA = pack2(bt[lid], bt[lid + 32]);
    unsigned long long zbB = pack2(bt[lid + 64], bt[lid + 96]);
    float zb4 = v4 ? bt[t4] : -1e30f;

    size_t word0 = (size_t)warp * WPW;

    // prefetch first word's h
    const float4* hp = reinterpret_cast<const float4*>(g_h + word0 * 12);
    float4 c0 = hp[0], c1 = hp[1], c2 = hp[2];

#pragma unroll 1
    for (int w = 0; w < WPW; w++) {
        size_t word = word0 + w;

        float o[12] = {c0.x, c0.y, c0.z, c0.w, c1.x, c1.y, c1.z, c1.w,
                       c2.x, c2.y, c2.z, c2.w};

        if (w + 1 < WPW) {
            const float4* hn = reinterpret_cast<const float4*>(g_h + (word + 1) * 12);
            c0 = hn[0]; c1 = hn[1]; c2 = hn[2];
        }

        unsigned long long zA = zbA, zB = zbB;
        float z4 = zb4;
#pragma unroll
        for (int j = 0; j < 12; j++) {
            unsigned long long oo = pack2(o[j], o[j]);
            zA = fma2(oo, wpA[j], zA);
            zB = fma2(oo, wpB[j], zB);
            z4 = fmaf(o[j], w4[j], z4);
        }

        float z0, z1, z2, z3;
        unpack2(z0, z1, zA);
        unpack2(z2, z3, zB);

        float sum = __expf(z0) + __expf(z1) + __expf(z2) + __expf(z3) + __expf(z4);
#pragma unroll
        for (int off = 16; off; off >>= 1)
            sum += __shfl_xor_sync(0xffffffffu, sum, off);
        float ld = __logf(sum);

        float* orow = out + word * T_;
        orow[lid]       = z0 - ld;
        orow[lid + 32]  = z1 - ld;
        orow[lid + 64]  = z2 - ld;
        orow[lid + 96]  = z3 - ld;
        if (v4) orow[lid + 128] = z4 - ld;
    }
}

// ---------------------------------------------------------------------------
// Host launcher. Inputs resolved by element count.
// ---------------------------------------------------------------------------
extern "C" void kernel_launch(void* const* d_in, const int* in_sizes, int n_in,
                              void* d_out, int out_size)
{
    int i_widx = -1, i_cidx = -1, i_wemb = -1, i_cemb = -1, i_wc = -1, i_bc = -1;
    int i_wih_f = -1, i_whh_f = -1, i_b_f = -1, i_wih_b = -1, i_whh_b = -1, i_b_b = -1;
    int i_wt = -1, i_bt = -1;

    for (int i = 0; i < n_in; i++) {
        switch (in_sizes[i]) {
            case B_ * S_:            i_widx = i; break;
            case B_ * S_ * LP_:      i_cidx = i; break;
            case V_ * WE_:           i_wemb = i; break;
            case A_ * CE_:           i_cemb = i; break;
            case LF_ * K_ * CE_:     i_wc = i;   break;
            case LF_:                i_bc = i;   break;
            case 4 * H_ * D_:        if (i_wih_f < 0) i_wih_f = i; else i_wih_b = i; break;
            case 4 * H_ * H_:        if (i_whh_f < 0) i_whh_f = i; else i_whh_b = i; break;
            case 4 * H_:             if (i_b_f   < 0) i_b_f   = i; else i_b_b   = i; break;
            case T_ * 2 * H_:        i_wt = i;   break;
            case T_:                 i_bt = i;   break;
            default: break;
        }
    }

    const int*   word_idx = (const int*)  d_in[i_widx];
    const int*   char_idx = (const int*)  d_in[i_cidx];
    const float* word_emb = (const float*)d_in[i_wemb];
    const float* char_emb = (const float*)d_in[i_cemb];
    const float* Wc       = (const float*)d_in[i_wc];
    const float* bc       = (const float*)d_in[i_bc];
    const float* Wih_f    = (const float*)d_in[i_wih_f];
    const float* Whh_f    = (const float*)d_in[i_whh_f];
    const float* b_f      = (const float*)d_in[i_b_f];
    const float* Wih_b    = (const float*)d_in[i_wih_b];
    const float* Whh_b    = (const float*)d_in[i_whh_b];
    const float* b_b      = (const float*)d_in[i_b_b];
    const float* Wt       = (const float*)d_in[i_wt];
    const float* bt       = (const float*)d_in[i_bt];
    float*       out      = (float*)d_out;

    pd_kernel<<<10, 128>>>(char_emb, Wc, bc);

    embed_cnn_kernel<<<B_ * S_ / 256, 256>>>(word_idx, char_idx, word_emb,
                                             Wih_f, b_f, Wih_b, b_b);

    lstm_kernel<<<(2 * B_ * 32) / 128, 128>>>(Whh_f, Whh_b);

    proj_softmax_kernel<<<B_ * S_ / (8 * WPW), 256>>>(Wt, bt, out);
}